// round 1
// baseline (speedup 1.0000x reference)
#include <cuda_runtime.h>
#include <math.h>

#define N_NODES 50000
#define N_EDGES 600000
#define N_RELS  500
#define DIM     128

// ---- scratch (no allocations allowed) ----
__device__ __align__(16) float g_m_node[N_NODES * DIM];   // node messages
__device__ __align__(16) float g_m_rel[N_RELS * DIM];     // rel messages
__device__ float g_s_src[N_NODES];
__device__ float g_s_tgt[N_NODES];
__device__ float g_s_rel[N_RELS];
__device__ float g_dummy[N_RELS];
__device__ float g_scores[N_EDGES];
__device__ float g_ex[N_EDGES];
__device__ int   g_segmax[N_NODES];   // float-as-orderable-int
__device__ float g_denom[N_NODES];

// ---------------------------------------------------------------------------
__global__ void k_init(float* __restrict__ out) {
    int stride = gridDim.x * blockDim.x;
    int i = blockIdx.x * blockDim.x + threadIdx.x;
    for (int idx = i; idx < N_NODES * DIM; idx += stride) out[idx] = 0.f;
    for (int idx = i; idx < N_NODES; idx += stride) {
        g_segmax[idx] = (int)0xFF800000u;  // -inf bits
        g_denom[idx]  = 0.f;
    }
}

// ---------------------------------------------------------------------------
// Generic row transform: m = x @ W^T + b ; s1 = x . v1 ; s2 = x . v2
// mode 0 -> nodes (g_m_node, g_s_src, g_s_tgt); mode 1 -> rels (g_m_rel, g_s_rel, g_dummy)
// W is staged transposed in smem (row stride 132 floats) for conflict-free
// float4 reads; each warp register-blocks 4 rows to amortize the Wt load.
__global__ void k_precomp(const float* __restrict__ X, int n_rows,
                          const float* __restrict__ W, const float* __restrict__ b,
                          const float* __restrict__ v1, const float* __restrict__ v2,
                          int mode) {
    extern __shared__ float sm[];
    float* Wt  = sm;                    // 128*132
    float* xs  = Wt + DIM * 132;        // 32*128
    float* sv1 = xs + 32 * DIM;         // 128
    float* sv2 = sv1 + DIM;             // 128

    float* out_m  = (mode == 0) ? g_m_node : g_m_rel;
    float* out_s1 = (mode == 0) ? g_s_src  : g_s_rel;
    float* out_s2 = (mode == 0) ? g_s_tgt  : g_dummy;

    int tid = threadIdx.x;
    for (int idx = tid; idx < DIM * DIM; idx += blockDim.x) {
        int j = idx >> 7, k = idx & 127;
        Wt[k * 132 + j] = W[idx];
    }
    for (int k = tid; k < DIM; k += blockDim.x) { sv1[k] = v1[k]; sv2[k] = v2[k]; }
    __syncthreads();

    int warp = tid >> 5, lane = tid & 31;
    float4 bj = ((const float4*)b)[lane];
    const float4* Wt4 = (const float4*)Wt;   // row stride = 33 float4

    for (int base = blockIdx.x * 32; base < n_rows; base += gridDim.x * 32) {
        __syncthreads();
        for (int idx = tid; idx < 32 * (DIM / 4); idx += blockDim.x) {
            int n = idx >> 5;
            int c = idx & 31;
            int row = base + n;
            float4 v = make_float4(0.f, 0.f, 0.f, 0.f);
            if (row < n_rows) v = ((const float4*)X)[row * (DIM / 4) + c];
            ((float4*)xs)[n * (DIM / 4) + c] = v;
        }
        __syncthreads();

        int n0 = warp * 4;
        const float* x0 = xs + (n0 + 0) * DIM;
        const float* x1 = xs + (n0 + 1) * DIM;
        const float* x2 = xs + (n0 + 2) * DIM;
        const float* x3 = xs + (n0 + 3) * DIM;
        float4 a0 = bj, a1 = bj, a2 = bj, a3 = bj;
#pragma unroll 4
        for (int k = 0; k < DIM; k++) {
            float4 wv = Wt4[k * 33 + lane];
            float xa = x0[k], xb = x1[k], xc = x2[k], xd = x3[k];
            a0.x += wv.x * xa; a0.y += wv.y * xa; a0.z += wv.z * xa; a0.w += wv.w * xa;
            a1.x += wv.x * xb; a1.y += wv.y * xb; a1.z += wv.z * xb; a1.w += wv.w * xb;
            a2.x += wv.x * xc; a2.y += wv.y * xc; a2.z += wv.z * xc; a2.w += wv.w * xc;
            a3.x += wv.x * xd; a3.y += wv.y * xd; a3.z += wv.z * xd; a3.w += wv.w * xd;
        }
#pragma unroll
        for (int nn = 0; nn < 4; nn++) {
            int row = base + n0 + nn;
            if (row >= n_rows) break;
            float4 av = (nn == 0) ? a0 : (nn == 1) ? a1 : (nn == 2) ? a2 : a3;
            ((float4*)out_m)[row * (DIM / 4) + lane] = av;
            const float* xr = xs + (n0 + nn) * DIM;
            float p1 = 0.f, p2 = 0.f;
#pragma unroll
            for (int q = 0; q < 4; q++) {
                int k = lane * 4 + q;
                float xv = xr[k];
                p1 += xv * sv1[k];
                p2 += xv * sv2[k];
            }
#pragma unroll
            for (int o = 16; o; o >>= 1) {
                p1 += __shfl_down_sync(0xffffffffu, p1, o);
                p2 += __shfl_down_sync(0xffffffffu, p2, o);
            }
            if (lane == 0) { out_s1[row] = p1; out_s2[row] = p2; }
        }
    }
}

// ---------------------------------------------------------------------------
__global__ void k_edge_max(const int* __restrict__ src, const int* __restrict__ dst,
                           const int* __restrict__ rel, const float* __restrict__ attn_b) {
    int e = blockIdx.x * blockDim.x + threadIdx.x;
    if (e >= N_EDGES) return;
    int d = dst[e];
    float sc = g_s_src[src[e]] + g_s_tgt[d] + g_s_rel[rel[e]] + attn_b[0];
    g_scores[e] = sc;
    if (sc >= 0.f) atomicMax(&g_segmax[d], __float_as_int(sc));
    else           atomicMin((unsigned int*)&g_segmax[d], __float_as_uint(sc));
}

__global__ void k_edge_sum(const int* __restrict__ dst) {
    int e = blockIdx.x * blockDim.x + threadIdx.x;
    if (e >= N_EDGES) return;
    int d = dst[e];
    float mx = __int_as_float(g_segmax[d]);
    float ex = expf(g_scores[e] - mx);
    g_ex[e] = ex;
    atomicAdd(&g_denom[d], ex);
}

// one warp per edge: gather m_node[src]+m_rel[rel], scatter-add alpha*msg to out[dst]
__global__ void k_edge_agg(const int* __restrict__ src, const int* __restrict__ dst,
                           const int* __restrict__ rel, float* __restrict__ out) {
    int gid = blockIdx.x * blockDim.x + threadIdx.x;
    int e = gid >> 5;
    if (e >= N_EDGES) return;
    int lane = gid & 31;
    int s = src[e], d = dst[e], r = rel[e];
    float alpha = g_ex[e] / g_denom[d];
    float4 mv = ((const float4*)g_m_node)[s * (DIM / 4) + lane];
    float4 rv = ((const float4*)g_m_rel)[r * (DIM / 4) + lane];
    float* o = out + (size_t)d * DIM + lane * 4;
    atomicAdd(o + 0, alpha * (mv.x + rv.x));
    atomicAdd(o + 1, alpha * (mv.y + rv.y));
    atomicAdd(o + 2, alpha * (mv.z + rv.z));
    atomicAdd(o + 3, alpha * (mv.w + rv.w));
}

__global__ void k_final(const float* __restrict__ node_emb, float* __restrict__ out) {
    int gid = blockIdx.x * blockDim.x + threadIdx.x;
    int n = gid >> 5;
    if (n >= N_NODES) return;
    int lane = gid & 31;
    if (g_denom[n] == 0.f) {
        ((float4*)out)[n * (DIM / 4) + lane] = ((const float4*)node_emb)[n * (DIM / 4) + lane];
    }
}

// ---------------------------------------------------------------------------
extern "C" void kernel_launch(void* const* d_in, const int* in_sizes, int n_in,
                              void* d_out, int out_size) {
    const float* node_emb = (const float*)d_in[0];
    const float* rel_emb  = (const float*)d_in[1];
    const float* Wn       = (const float*)d_in[2];
    const float* bn       = (const float*)d_in[3];
    const float* Wr       = (const float*)d_in[4];
    const float* br       = (const float*)d_in[5];
    const float* attn_w   = (const float*)d_in[6];
    const float* attn_b   = (const float*)d_in[7];
    const int*   src      = (const int*)d_in[8];
    const int*   dst      = (const int*)d_in[9];
    const int*   rel      = (const int*)d_in[10];
    float* out = (float*)d_out;

    const int SMEM = (DIM * 132 + 32 * DIM + 2 * DIM) * (int)sizeof(float);  // 84,992 B
    cudaFuncSetAttribute(k_precomp, cudaFuncAttributeMaxDynamicSharedMemorySize, SMEM);

    k_init<<<2048, 256>>>(out);
    k_precomp<<<296, 256, SMEM>>>(node_emb, N_NODES, Wn, bn, attn_w, attn_w + DIM, 0);
    k_precomp<<<16, 256, SMEM>>>(rel_emb, N_RELS, Wr, br, attn_w + 2 * DIM, attn_w + 2 * DIM, 1);

    int eb = (N_EDGES + 255) / 256;
    k_edge_max<<<eb, 256>>>(src, dst, rel, attn_b);
    k_edge_sum<<<eb, 256>>>(dst);
    k_edge_agg<<<(N_EDGES * 32 + 255) / 256, 256>>>(src, dst, rel, out);
    k_final<<<(N_NODES * 32 + 255) / 256, 256>>>(node_emb, out);
}

// round 3
// speedup vs baseline: 2.0143x; 2.0143x over previous
#include <cuda_runtime.h>
#include <math.h>

#define N_NODES 50000
#define N_EDGES 600000
#define N_RELS  500
#define DIM     128
#define SCAN_CHUNKS ((N_NODES + 1023) / 1024)   // 49

// ---- scratch (no allocations allowed) ----
__device__ __align__(16) float g_m_node[N_NODES * DIM];
__device__ __align__(16) float g_m_rel[N_RELS * DIM];
__device__ float g_s_src[N_NODES];
__device__ float g_s_tgt[N_NODES];
__device__ float g_s_rel[N_RELS];
__device__ float g_dummy[N_RELS];
__device__ int   g_count[N_NODES];
__device__ int   g_offset[N_NODES + 1];
__device__ int   g_cursor[N_NODES];
__device__ int   g_blocksum[SCAN_CHUNKS];
__device__ int   g_carry[SCAN_CHUNKS];
__device__ unsigned g_epack[N_EDGES];   // src | rel<<16  (src<65536, rel<500)

// ---------------------------------------------------------------------------
__device__ __forceinline__ unsigned long long fma2(unsigned long long a,
                                                   unsigned long long b,
                                                   unsigned long long c) {
    unsigned long long d;
    asm("fma.rn.f32x2 %0, %1, %2, %3;" : "=l"(d) : "l"(a), "l"(b), "l"(c));
    return d;
}
__device__ __forceinline__ unsigned long long pack2(float x) {
    unsigned long long d;
    asm("mov.b64 %0, {%1, %1};" : "=l"(d) : "r"(__float_as_uint(x)));
    return d;
}
union F4U { float4 f4; unsigned long long u[2]; };

// ---------------------------------------------------------------------------
// Row transform: m = x @ W^T + b ; s1 = x.v1 ; s2 = x.v2
// One block = 64 rows (8 warps x 8 rows). W^T staged in smem, f32x2 FFMA.
__global__ void k_precomp(const float* __restrict__ X, int n_rows,
                          const float* __restrict__ W, const float* __restrict__ b,
                          const float* __restrict__ v1, const float* __restrict__ v2,
                          int mode) {
    extern __shared__ float sm[];
    float* Wt  = sm;                    // 128*132
    float* xs  = Wt + DIM * 132;        // 64*128
    float* sv1 = xs + 64 * DIM;         // 128
    float* sv2 = sv1 + DIM;             // 128

    float* out_m  = (mode == 0) ? g_m_node : g_m_rel;
    float* out_s1 = (mode == 0) ? g_s_src  : g_s_rel;
    float* out_s2 = (mode == 0) ? g_s_tgt  : g_dummy;

    int tid = threadIdx.x;
    for (int idx = tid; idx < DIM * DIM; idx += blockDim.x) {
        int j = idx >> 7, k = idx & 127;
        Wt[k * 132 + j] = W[idx];
    }
    for (int k = tid; k < DIM; k += blockDim.x) { sv1[k] = v1[k]; sv2[k] = v2[k]; }

    int base = blockIdx.x * 64;
    for (int idx = tid; idx < 64 * (DIM / 4); idx += blockDim.x) {
        int n = idx >> 5, c = idx & 31;
        int row = base + n;
        float4 v = make_float4(0.f, 0.f, 0.f, 0.f);
        if (row < n_rows) v = ((const float4*)X)[row * (DIM / 4) + c];
        ((float4*)xs)[n * (DIM / 4) + c] = v;
    }
    __syncthreads();

    int warp = tid >> 5, lane = tid & 31;
    F4U bu; bu.f4 = ((const float4*)b)[lane];

    unsigned long long alo[8], ahi[8];
#pragma unroll
    for (int i = 0; i < 8; i++) { alo[i] = bu.u[0]; ahi[i] = bu.u[1]; }

    int n0 = warp * 8;
    const float* xr0 = xs + n0 * DIM;
    const float4* Wt4 = (const float4*)Wt;   // row stride 33 float4

#pragma unroll 4
    for (int k = 0; k < DIM; k++) {
        F4U w; w.f4 = Wt4[k * 33 + lane];
#pragma unroll
        for (int i = 0; i < 8; i++) {
            unsigned long long xx = pack2(xr0[i * DIM + k]);
            alo[i] = fma2(w.u[0], xx, alo[i]);
            ahi[i] = fma2(w.u[1], xx, ahi[i]);
        }
    }

#pragma unroll
    for (int i = 0; i < 8; i++) {
        int row = base + n0 + i;
        if (row >= n_rows) break;
        F4U o; o.u[0] = alo[i]; o.u[1] = ahi[i];
        ((float4*)out_m)[row * (DIM / 4) + lane] = o.f4;
        const float* xr = xr0 + i * DIM;
        float p1 = 0.f, p2 = 0.f;
#pragma unroll
        for (int q = 0; q < 4; q++) {
            int k = lane * 4 + q;
            float xv = xr[k];
            p1 += xv * sv1[k];
            p2 += xv * sv2[k];
        }
#pragma unroll
        for (int o2 = 16; o2; o2 >>= 1) {
            p1 += __shfl_down_sync(0xffffffffu, p1, o2);
            p2 += __shfl_down_sync(0xffffffffu, p2, o2);
        }
        if (lane == 0) { out_s1[row] = p1; out_s2[row] = p2; }
    }
}

// ---------------------------------------------------------------------------
__global__ void k_zero() {
    int i = blockIdx.x * blockDim.x + threadIdx.x;
    if (i < N_NODES) g_count[i] = 0;
}

__global__ void k_hist(const int* __restrict__ dst) {
    int e = blockIdx.x * blockDim.x + threadIdx.x;
    if (e < N_EDGES) atomicAdd(&g_count[dst[e]], 1);
}

__global__ void k_scan_local() {
    __shared__ int s[1024];
    int tid = threadIdx.x;
    int idx = blockIdx.x * 1024 + tid;
    int v = (idx < N_NODES) ? g_count[idx] : 0;
    s[tid] = v;
    __syncthreads();
#pragma unroll
    for (int off = 1; off < 1024; off <<= 1) {
        int t = (tid >= off) ? s[tid - off] : 0;
        __syncthreads();
        s[tid] += t;
        __syncthreads();
    }
    if (idx < N_NODES) g_offset[idx] = s[tid] - v;   // exclusive within chunk
    if (tid == 1023) g_blocksum[blockIdx.x] = s[tid];
}

__global__ void k_scan_carry() {
    if (threadIdx.x == 0 && blockIdx.x == 0) {
        int run = 0;
        for (int c = 0; c < SCAN_CHUNKS; c++) {
            g_carry[c] = run;
            run += g_blocksum[c];
        }
        g_offset[N_NODES] = N_EDGES;
    }
}

__global__ void k_scan_add() {
    int idx = blockIdx.x * blockDim.x + threadIdx.x;
    if (idx < N_NODES) {
        int v = g_offset[idx] + g_carry[idx >> 10];
        g_offset[idx] = v;
        g_cursor[idx] = v;
    }
}

__global__ void k_fill(const int* __restrict__ src, const int* __restrict__ dst,
                       const int* __restrict__ rel) {
    int e = blockIdx.x * blockDim.x + threadIdx.x;
    if (e >= N_EDGES) return;
    int pos = atomicAdd(&g_cursor[dst[e]], 1);
    g_epack[pos] = (unsigned)src[e] | ((unsigned)rel[e] << 16);
}

// ---------------------------------------------------------------------------
// One warp per dst node: fused softmax + weighted aggregate + fallback.
__global__ void k_node_agg(const float* __restrict__ node_emb,
                           const float* __restrict__ attn_b,
                           float* __restrict__ out) {
    int gid = blockIdx.x * blockDim.x + threadIdx.x;
    int n = gid >> 5;
    if (n >= N_NODES) return;
    int lane = gid & 31;
    int beg = g_offset[n], end = g_offset[n + 1];
    float4 res;
    if (end > beg) {
        float st = g_s_tgt[n] + attn_b[0];
        float4 acc = make_float4(0.f, 0.f, 0.f, 0.f);
        float denom = 0.f;
        for (int e = beg; e < end; e++) {
            unsigned p = g_epack[e];
            int s = p & 0xFFFF;
            int r = p >> 16;
            float ex = __expf(g_s_src[s] + g_s_rel[r] + st);
            float4 mv = ((const float4*)g_m_node)[s * (DIM / 4) + lane];
            float4 rv = ((const float4*)g_m_rel)[r * (DIM / 4) + lane];
            acc.x += ex * (mv.x + rv.x);
            acc.y += ex * (mv.y + rv.y);
            acc.z += ex * (mv.z + rv.z);
            acc.w += ex * (mv.w + rv.w);
            denom += ex;
        }
        float inv = 1.f / denom;
        res = make_float4(acc.x * inv, acc.y * inv, acc.z * inv, acc.w * inv);
    } else {
        res = ((const float4*)node_emb)[n * (DIM / 4) + lane];
    }
    ((float4*)out)[n * (DIM / 4) + lane] = res;
}

// ---------------------------------------------------------------------------
extern "C" void kernel_launch(void* const* d_in, const int* in_sizes, int n_in,
                              void* d_out, int out_size) {
    const float* node_emb = (const float*)d_in[0];
    const float* rel_emb  = (const float*)d_in[1];
    const float* Wn       = (const float*)d_in[2];
    const float* bn       = (const float*)d_in[3];
    const float* Wr       = (const float*)d_in[4];
    const float* br       = (const float*)d_in[5];
    const float* attn_w   = (const float*)d_in[6];
    const float* attn_b   = (const float*)d_in[7];
    const int*   src      = (const int*)d_in[8];
    const int*   dst      = (const int*)d_in[9];
    const int*   rel      = (const int*)d_in[10];
    float* out = (float*)d_out;

    const int SMEM = (DIM * 132 + 64 * DIM + 2 * DIM) * (int)sizeof(float);  // 101,376 B
    cudaFuncSetAttribute(k_precomp, cudaFuncAttributeMaxDynamicSharedMemorySize, SMEM);

    int eb = (N_EDGES + 255) / 256;
    int nb = (N_NODES + 255) / 256;

    k_zero<<<nb, 256>>>();
    k_precomp<<<(N_NODES + 63) / 64, 256, SMEM>>>(node_emb, N_NODES, Wn, bn,
                                                  attn_w, attn_w + DIM, 0);
    k_precomp<<<(N_RELS + 63) / 64, 256, SMEM>>>(rel_emb, N_RELS, Wr, br,
                                                 attn_w + 2 * DIM, attn_w + 2 * DIM, 1);
    k_hist<<<eb, 256>>>(dst);
    k_scan_local<<<SCAN_CHUNKS, 1024>>>();
    k_scan_carry<<<1, 32>>>();
    k_scan_add<<<nb, 256>>>();
    k_fill<<<eb, 256>>>(src, dst, rel);
    k_node_agg<<<(N_NODES * 32 + 255) / 256, 256>>>(node_emb, attn_b, out);
}